// round 1
// baseline (speedup 1.0000x reference)
#include <cuda_runtime.h>
#include <math.h>

#define BATCH  16
#define NSEQ   1024
#define DMODEL 256
#define HEADS  8
#define DKDIM  32
#define NUMREL 3969

// Scratch (allocation-free rule: __device__ globals)
__device__ float g_q[BATCH * HEADS * NSEQ * DKDIM];
__device__ float g_k[BATCH * HEADS * NSEQ * DKDIM];
__device__ float g_v[BATCH * HEADS * NSEQ * DKDIM];
__device__ float g_o[BATCH * NSEQ * DMODEL];

// ---------------------------------------------------------------------------
// GEMM: C = A @ W^T + bias.  A:[M,256] W:[256,256] row-major. 64x64 tile,
// BK=16, 256 threads, 4x4 register tile.
// proj variant remaps output column c=(h*32+d), row m=(b*1024+n) into
// [b,h,n,d] scratch selected by `which`.
// ---------------------------------------------------------------------------
__global__ __launch_bounds__(256) void proj_qkv_kernel(
    const float* __restrict__ A, const float* __restrict__ W,
    const float* __restrict__ bias, int which)
{
    __shared__ float As[16][65];
    __shared__ float Ws[16][65];

    const int K = DMODEL;
    int tid = threadIdx.x;
    int ty = tid >> 4, tx = tid & 15;
    int m0 = blockIdx.y * 64, n0 = blockIdx.x * 64;

    int lr = tid >> 2;          // 0..63
    int lc = (tid & 3) << 2;    // 0,4,8,12
    const float* Ap = A + (size_t)(m0 + lr) * K + lc;
    const float* Wp = W + (size_t)(n0 + lr) * K + lc;

    float acc[4][4];
#pragma unroll
    for (int i = 0; i < 4; i++)
#pragma unroll
        for (int j = 0; j < 4; j++) acc[i][j] = 0.f;

    for (int k0 = 0; k0 < K; k0 += 16) {
        float4 a = *(const float4*)(Ap + k0);
        float4 w = *(const float4*)(Wp + k0);
        __syncthreads();
        As[lc + 0][lr] = a.x; As[lc + 1][lr] = a.y;
        As[lc + 2][lr] = a.z; As[lc + 3][lr] = a.w;
        Ws[lc + 0][lr] = w.x; Ws[lc + 1][lr] = w.y;
        Ws[lc + 2][lr] = w.z; Ws[lc + 3][lr] = w.w;
        __syncthreads();
#pragma unroll
        for (int kk = 0; kk < 16; kk++) {
            float av[4], wv[4];
#pragma unroll
            for (int i = 0; i < 4; i++) av[i] = As[kk][4 * ty + i];
#pragma unroll
            for (int j = 0; j < 4; j++) wv[j] = Ws[kk][4 * tx + j];
#pragma unroll
            for (int i = 0; i < 4; i++)
#pragma unroll
                for (int j = 0; j < 4; j++)
                    acc[i][j] = fmaf(av[i], wv[j], acc[i][j]);
        }
    }

    float* dst = (which == 0) ? g_q : (which == 1) ? g_k : g_v;
#pragma unroll
    for (int i = 0; i < 4; i++) {
        int m = m0 + 4 * ty + i;
        int b = m >> 10, n = m & 1023;
#pragma unroll
        for (int j = 0; j < 4; j++) {
            int c = n0 + 4 * tx + j;
            int h = c >> 5, d = c & 31;
            dst[(((size_t)(b * HEADS + h)) * NSEQ + n) * DKDIM + d] =
                acc[i][j] + bias[c];
        }
    }
}

__global__ __launch_bounds__(256) void out_proj_kernel(
    const float* __restrict__ W, const float* __restrict__ bias,
    float* __restrict__ C)
{
    __shared__ float As[16][65];
    __shared__ float Ws[16][65];

    const int K = DMODEL;
    int tid = threadIdx.x;
    int ty = tid >> 4, tx = tid & 15;
    int m0 = blockIdx.y * 64, n0 = blockIdx.x * 64;

    int lr = tid >> 2;
    int lc = (tid & 3) << 2;
    const float* Ap = g_o + (size_t)(m0 + lr) * K + lc;
    const float* Wp = W + (size_t)(n0 + lr) * K + lc;

    float acc[4][4];
#pragma unroll
    for (int i = 0; i < 4; i++)
#pragma unroll
        for (int j = 0; j < 4; j++) acc[i][j] = 0.f;

    for (int k0 = 0; k0 < K; k0 += 16) {
        float4 a = *(const float4*)(Ap + k0);
        float4 w = *(const float4*)(Wp + k0);
        __syncthreads();
        As[lc + 0][lr] = a.x; As[lc + 1][lr] = a.y;
        As[lc + 2][lr] = a.z; As[lc + 3][lr] = a.w;
        Ws[lc + 0][lr] = w.x; Ws[lc + 1][lr] = w.y;
        Ws[lc + 2][lr] = w.z; Ws[lc + 3][lr] = w.w;
        __syncthreads();
#pragma unroll
        for (int kk = 0; kk < 16; kk++) {
            float av[4], wv[4];
#pragma unroll
            for (int i = 0; i < 4; i++) av[i] = As[kk][4 * ty + i];
#pragma unroll
            for (int j = 0; j < 4; j++) wv[j] = Ws[kk][4 * tx + j];
#pragma unroll
            for (int i = 0; i < 4; i++)
#pragma unroll
                for (int j = 0; j < 4; j++)
                    acc[i][j] = fmaf(av[i], wv[j], acc[i][j]);
        }
    }

#pragma unroll
    for (int i = 0; i < 4; i++) {
        int m = m0 + 4 * ty + i;
#pragma unroll
        for (int j = 0; j < 4; j++) {
            int c = n0 + 4 * tx + j;
            C[(size_t)m * DMODEL + c] = acc[i][j] + bias[c];
        }
    }
}

// ---------------------------------------------------------------------------
// Fused flash attention with relative-position bias.
// Block: 64 query rows of one (b,h). 256 threads as 16x16; thread (ty,tx)
// owns S rows 4ty..4ty+3, cols 4tx..4tx+3 per 64-key tile.
// Row softmax stats reduced over the 16 tx lanes (xor shuffles 1,2,4,8).
// ---------------------------------------------------------------------------
__global__ __launch_bounds__(256) void attn_kernel(
    const float* __restrict__ bias_table, const int* __restrict__ rel_index)
{
    __shared__ float Qs[64][DKDIM + 1];
    __shared__ float Ks[64][DKDIM + 1];
    __shared__ float Vs[64][DKDIM];
    __shared__ float Ps[64][64];

    const float SCALE = 0.17677669529663687f;  // 1/sqrt(32)

    int bh = blockIdx.y;             // 0..127
    int h = bh & (HEADS - 1);
    int b = bh >> 3;
    int qbase = blockIdx.x * 64;
    int tid = threadIdx.x;
    int ty = tid >> 4, tx = tid & 15;

    const float* qptr = g_q + (size_t)bh * NSEQ * DKDIM;
    const float* kptr = g_k + (size_t)bh * NSEQ * DKDIM;
    const float* vptr = g_v + (size_t)bh * NSEQ * DKDIM;
    const float* brow = bias_table + h * NUMREL;

    // Load Q tile (64x32) into padded SMEM
    {
        int r = tid >> 2;
        int d0 = (tid & 3) << 3;
        const float* src = qptr + (size_t)(qbase + r) * DKDIM + d0;
        float4 v0 = *(const float4*)src;
        float4 v1 = *(const float4*)(src + 4);
        Qs[r][d0 + 0] = v0.x; Qs[r][d0 + 1] = v0.y;
        Qs[r][d0 + 2] = v0.z; Qs[r][d0 + 3] = v0.w;
        Qs[r][d0 + 4] = v1.x; Qs[r][d0 + 5] = v1.y;
        Qs[r][d0 + 6] = v1.z; Qs[r][d0 + 7] = v1.w;
    }

    float mrow[4], lrow[4], acc_o[4][2];
#pragma unroll
    for (int i = 0; i < 4; i++) {
        mrow[i] = -1e30f; lrow[i] = 0.f;
        acc_o[i][0] = 0.f; acc_o[i][1] = 0.f;
    }

    for (int kb = 0; kb < NSEQ; kb += 64) {
        // stage K,V tile
        int r = tid >> 2;
        int d0 = (tid & 3) << 3;
        const float* ks = kptr + (size_t)(kb + r) * DKDIM + d0;
        const float* vs = vptr + (size_t)(kb + r) * DKDIM + d0;
        float4 k0 = *(const float4*)ks;
        float4 k1 = *(const float4*)(ks + 4);
        float4 w0 = *(const float4*)vs;
        float4 w1 = *(const float4*)(vs + 4);
        __syncthreads();  // previous tile's PV readers done
        Ks[r][d0 + 0] = k0.x; Ks[r][d0 + 1] = k0.y;
        Ks[r][d0 + 2] = k0.z; Ks[r][d0 + 3] = k0.w;
        Ks[r][d0 + 4] = k1.x; Ks[r][d0 + 5] = k1.y;
        Ks[r][d0 + 6] = k1.z; Ks[r][d0 + 7] = k1.w;
        *(float4*)&Vs[r][d0] = w0;
        *(float4*)&Vs[r][d0 + 4] = w1;
        __syncthreads();

        // S = Q K^T (4x4 register tile)
        float acc[4][4];
#pragma unroll
        for (int i = 0; i < 4; i++)
#pragma unroll
            for (int j = 0; j < 4; j++) acc[i][j] = 0.f;
#pragma unroll
        for (int d = 0; d < DKDIM; d++) {
            float av[4], bv[4];
#pragma unroll
            for (int i = 0; i < 4; i++) av[i] = Qs[4 * ty + i][d];
#pragma unroll
            for (int j = 0; j < 4; j++) bv[j] = Ks[4 * tx + j][d];
#pragma unroll
            for (int i = 0; i < 4; i++)
#pragma unroll
                for (int j = 0; j < 4; j++)
                    acc[i][j] = fmaf(av[i], bv[j], acc[i][j]);
        }

        // scale + relative-position bias
        float p[4][4];
#pragma unroll
        for (int i = 0; i < 4; i++) {
            int qrow = qbase + 4 * ty + i;
            int4 idx = *(const int4*)(rel_index + (size_t)qrow * NSEQ + kb + 4 * tx);
            p[i][0] = fmaf(acc[i][0], SCALE, __ldg(brow + idx.x));
            p[i][1] = fmaf(acc[i][1], SCALE, __ldg(brow + idx.y));
            p[i][2] = fmaf(acc[i][2], SCALE, __ldg(brow + idx.z));
            p[i][3] = fmaf(acc[i][3], SCALE, __ldg(brow + idx.w));
        }

        // online softmax update per row
#pragma unroll
        for (int i = 0; i < 4; i++) {
            float tmax = fmaxf(fmaxf(p[i][0], p[i][1]), fmaxf(p[i][2], p[i][3]));
            tmax = fmaxf(tmax, __shfl_xor_sync(0xffffffffu, tmax, 1));
            tmax = fmaxf(tmax, __shfl_xor_sync(0xffffffffu, tmax, 2));
            tmax = fmaxf(tmax, __shfl_xor_sync(0xffffffffu, tmax, 4));
            tmax = fmaxf(tmax, __shfl_xor_sync(0xffffffffu, tmax, 8));
            float mnew = fmaxf(mrow[i], tmax);
            float factor = __expf(mrow[i] - mnew);
            mrow[i] = mnew;
            float rs = 0.f;
#pragma unroll
            for (int j = 0; j < 4; j++) {
                p[i][j] = __expf(p[i][j] - mnew);
                rs += p[i][j];
            }
            rs += __shfl_xor_sync(0xffffffffu, rs, 1);
            rs += __shfl_xor_sync(0xffffffffu, rs, 2);
            rs += __shfl_xor_sync(0xffffffffu, rs, 4);
            rs += __shfl_xor_sync(0xffffffffu, rs, 8);
            lrow[i] = lrow[i] * factor + rs;
            acc_o[i][0] *= factor;
            acc_o[i][1] *= factor;
            *(float4*)&Ps[4 * ty + i][4 * tx] =
                make_float4(p[i][0], p[i][1], p[i][2], p[i][3]);
        }
        __syncthreads();

        // O += P @ V  (thread owns rows 4ty+i, output cols 2tx..2tx+1)
#pragma unroll 4
        for (int kk = 0; kk < 64; kk += 4) {
            float4 pr[4];
#pragma unroll
            for (int i = 0; i < 4; i++)
                pr[i] = *(const float4*)&Ps[4 * ty + i][kk];
            float2 vv[4];
#pragma unroll
            for (int t = 0; t < 4; t++)
                vv[t] = *(const float2*)&Vs[kk + t][2 * tx];
#pragma unroll
            for (int i = 0; i < 4; i++) {
                acc_o[i][0] = fmaf(pr[i].x, vv[0].x, acc_o[i][0]);
                acc_o[i][1] = fmaf(pr[i].x, vv[0].y, acc_o[i][1]);
                acc_o[i][0] = fmaf(pr[i].y, vv[1].x, acc_o[i][0]);
                acc_o[i][1] = fmaf(pr[i].y, vv[1].y, acc_o[i][1]);
                acc_o[i][0] = fmaf(pr[i].z, vv[2].x, acc_o[i][0]);
                acc_o[i][1] = fmaf(pr[i].z, vv[2].y, acc_o[i][1]);
                acc_o[i][0] = fmaf(pr[i].w, vv[3].x, acc_o[i][0]);
                acc_o[i][1] = fmaf(pr[i].w, vv[3].y, acc_o[i][1]);
            }
        }
    }

    // normalize + write O in [B, N, H*dk] layout (ready for output GEMM)
#pragma unroll
    for (int i = 0; i < 4; i++) {
        float inv = 1.0f / lrow[i];
        int qrow = qbase + 4 * ty + i;
        float2 o2 = make_float2(acc_o[i][0] * inv, acc_o[i][1] * inv);
        *(float2*)(g_o + ((size_t)(b * NSEQ + qrow)) * DMODEL + h * DKDIM + 2 * tx) = o2;
    }
}

// ---------------------------------------------------------------------------
extern "C" void kernel_launch(void* const* d_in, const int* in_sizes, int n_in,
                              void* d_out, int out_size)
{
    const float* x          = (const float*)d_in[0];
    const float* Wq         = (const float*)d_in[1];
    const float* bq         = (const float*)d_in[2];
    const float* Wk         = (const float*)d_in[3];
    const float* bk         = (const float*)d_in[4];
    const float* Wv         = (const float*)d_in[5];
    const float* bv         = (const float*)d_in[6];
    const float* Wo         = (const float*)d_in[7];
    const float* bo         = (const float*)d_in[8];
    const float* bias_table = (const float*)d_in[9];
    const int*   rel_index  = (const int*)d_in[10];
    float* out = (float*)d_out;

    dim3 gthr(256);
    dim3 ggrid(DMODEL / 64, (BATCH * NSEQ) / 64);   // (4, 256)

    proj_qkv_kernel<<<ggrid, gthr>>>(x, Wq, bq, 0);
    proj_qkv_kernel<<<ggrid, gthr>>>(x, Wk, bk, 1);
    proj_qkv_kernel<<<ggrid, gthr>>>(x, Wv, bv, 2);

    attn_kernel<<<dim3(NSEQ / 64, BATCH * HEADS), 256>>>(bias_table, rel_index);

    out_proj_kernel<<<ggrid, gthr>>>(Wo, bo, out);
}